// round 7
// baseline (speedup 1.0000x reference)
#include <cuda_runtime.h>
#include <cuda_fp16.h>
#include <cstdint>
#include <math.h>

#define B_   16384
#define S_   6
#define D_   991
#define KD   992          // fp32 out-row stride for g_out
#define KH   1024         // padded K for half GEMM operands
#define G3   2973
#define NP   3072         // padded N
#define TM   128
#define TN   128
#define NT_  (NP / TN)    // 24 n-tiles
#define KCH  64           // K halfs per chunk (128 bytes/row)
#define NCHh (KH / KCH)   // 16 chunks
#define NST  4
#define STB  ((TM + TN) * 128)       // 32768 bytes per stage
#define SMEMB (NST * STB)            // 131072
#define GTHR 512                      // threads per GEMM CTA

// ------------------- scratch (device globals) ------------------------------
__device__ __half g_x  [(size_t)B_ * S_ * KH];
__device__ __half g_xg [(size_t)S_ * B_ * NP];
__device__ __half g_gh [(size_t)B_ * NP];
__device__ __half g_h  [(size_t)B_ * KH];
__device__ float  g_out[(size_t)B_ * KD];
__device__ __half g_Wih[(size_t)NP * KH];
__device__ __half g_Whh[(size_t)NP * KH];
__device__ float  g_bih[NP];
__device__ float  g_bhh[NP];
__device__ float  g_psum[32 * KD];
__device__ float  g_psq [32 * KD];
__device__ float  g_weff[2 * D_];
__device__ float  g_wbn [2 * KD];
__device__ float  g_shift[KD];
__device__ float  g_bbn [2];
// ragged-batch bookkeeping (permuted row space, sorted by descending seq_len)
__device__ int    g_idx[B_];    // position p -> batch b
__device__ int    g_sln[B_];    // position p -> seq_len
__device__ int    g_cnt[8];     // g_cnt[s] = #rows active at step s (prefix)

// --------------------------- helpers ---------------------------------------
__device__ __forceinline__ uint32_t smem_u32(const void* p) {
    uint32_t a;
    asm("{ .reg .u64 t; cvta.to.shared.u64 t, %1; cvt.u32.u64 %0, t; }" : "=r"(a) : "l"(p));
    return a;
}
__device__ __forceinline__ void cp_async16(uint32_t dst, const void* src) {
    asm volatile("cp.async.cg.shared.global [%0], [%1], 16;" :: "r"(dst), "l"(src) : "memory");
}
#define CP_COMMIT() asm volatile("cp.async.commit_group;" ::: "memory")
#define CP_WAIT(n)  asm volatile("cp.async.wait_group %0;" :: "n"(n) : "memory")

__device__ __forceinline__ void ldm4(uint32_t* r, uint32_t addr) {
    asm volatile("ldmatrix.sync.aligned.m8n8.x4.shared.b16 {%0,%1,%2,%3}, [%4];"
                 : "=r"(r[0]), "=r"(r[1]), "=r"(r[2]), "=r"(r[3]) : "r"(addr));
}
__device__ __forceinline__ void mma_h(float* c, const uint32_t* a, const uint32_t* b) {
    asm volatile(
        "mma.sync.aligned.m16n8k16.row.col.f32.f16.f16.f32 "
        "{%0,%1,%2,%3}, {%4,%5,%6,%7}, {%8,%9}, {%0,%1,%2,%3};"
        : "+f"(c[0]), "+f"(c[1]), "+f"(c[2]), "+f"(c[3])
        : "r"(a[0]), "r"(a[1]), "r"(a[2]), "r"(a[3]), "r"(b[0]), "r"(b[1]));
}

__device__ __forceinline__ float2 block_reduce2(float a, float b) {
    __shared__ float wa[8], wb[8];
    __shared__ float ra, rb;
    int lane = threadIdx.x & 31, w = threadIdx.x >> 5;
#pragma unroll
    for (int o = 16; o; o >>= 1) {
        a += __shfl_down_sync(0xffffffffu, a, o);
        b += __shfl_down_sync(0xffffffffu, b, o);
    }
    if (!lane) { wa[w] = a; wb[w] = b; }
    __syncthreads();
    if (threadIdx.x < 8) { a = wa[threadIdx.x]; b = wb[threadIdx.x]; }
    else { a = 0.f; b = 0.f; }
    if (w == 0) {
#pragma unroll
        for (int o = 4; o; o >>= 1) {
            a += __shfl_down_sync(0xffffffffu, a, o);
            b += __shfl_down_sync(0xffffffffu, b, o);
        }
    }
    if (threadIdx.x == 0) { ra = a; rb = b; }
    __syncthreads();
    return make_float2(ra, rb);
}

// --------------------------- deterministic counting sort --------------------
__global__ void __launch_bounds__(1024)
sort_kernel(const int* __restrict__ seq_len) {
    __shared__ int cnts[1024][6];   // 24 KB
    __shared__ int tot[6], base[6];
    const int tid = threadIdx.x;
    const int b0 = tid * 16;
    int lc[6] = {0, 0, 0, 0, 0, 0};
#pragma unroll
    for (int k = 0; k < 16; ++k) {
        int v = seq_len[b0 + k] - 1;     // 0..5
        lc[v]++;
    }
#pragma unroll
    for (int v = 0; v < 6; ++v) cnts[tid][v] = lc[v];
    __syncthreads();
    if (tid < 6) {
        int run = 0;
        for (int i = 0; i < 1024; ++i) {
            int c = cnts[i][tid];
            cnts[i][tid] = run;
            run += c;
        }
        tot[tid] = run;
    }
    __syncthreads();
    if (tid == 0) {
        int acc = 0;
        for (int v = 5; v >= 0; --v) { base[v] = acc; acc += tot[v]; }
        for (int s = 0; s < 6; ++s) {
            int c = 0;
            for (int v = s; v < 6; ++v) c += tot[v];
            g_cnt[s] = c;
        }
    }
    __syncthreads();
    int off[6];
#pragma unroll
    for (int v = 0; v < 6; ++v) off[v] = base[v] + cnts[tid][v];
#pragma unroll
    for (int k = 0; k < 16; ++k) {
        int b = b0 + k;
        int v = seq_len[b] - 1;
        int p = off[v]++;
        g_idx[p] = b;
        g_sln[p] = v + 1;
    }
}

// --------------------------- init / pack -----------------------------------
__global__ void pad_weights(const float* __restrict__ Wih, const float* __restrict__ Whh,
                            const float* __restrict__ bih, const float* __restrict__ bhh) {
    size_t i = (size_t)blockIdx.x * 256 + threadIdx.x;
    if (i >= (size_t)NP * KH) return;
    int r = (int)(i / KH), c = (int)(i - (size_t)r * KH);
    float vi = 0.f, vh = 0.f;
    if (r < G3 && c < D_) {
        vi = Wih[(size_t)r * D_ + c];
        vh = Whh[(size_t)r * D_ + c];
    }
    g_Wih[i] = __float2half_rn(vi);
    g_Whh[i] = __float2half_rn(vh);
    if (c == 0) {
        g_bih[r] = (r < G3) ? bih[r] : 0.f;
        g_bhh[r] = (r < G3) ? bhh[r] : 0.f;
    }
}

// --------------------------- embed + layernorm (permuted rows) -------------
__global__ void embed_ln(const int* __restrict__ ns, const int* __restrict__ fs,
                         const int* __restrict__ nfs, const int* __restrict__ ms,
                         const float* __restrict__ ntab, const float* __restrict__ ftab,
                         const float* __restrict__ nftab, const float* __restrict__ btab,
                         const float* __restrict__ lng, const float* __restrict__ lnb) {
    const int bid = blockIdx.x;          // row = s*B + p
    const int s = bid >> 14;
    const int p = bid & (B_ - 1);
    if (p >= g_cnt[s]) return;
    const int b = g_idx[p];
    __shared__ float srow[D_];
    const int q = b * S_ + s;
    const int ni = ns[q], fi = fs[q], nfi = nfs[q], mi = ms[q];
    float s1 = 0.f, s2 = 0.f;
    for (int d = threadIdx.x; d < D_; d += 256) {
        float v;
        if (d < 128)      v = ntab[(size_t)ni * 128 + d];
        else if (d < 212) v = ftab[(size_t)fi * 84 + (d - 128)];
        else if (d < 223) v = nftab[(size_t)nfi * 11 + (d - 212)];
        else              v = btab[(size_t)mi * 768 + (d - 223)];
        srow[d] = v;
        s1 += v; s2 += v * v;
    }
    float2 t = block_reduce2(s1, s2);
    const float mu  = t.x * (1.f / 991.f);
    const float var = fmaxf(t.y * (1.f / 991.f) - mu * mu, 0.f);
    const float rs  = rsqrtf(var + 1e-5f);
    __half* xr = g_x + (size_t)bid * KH;
    for (int d = threadIdx.x; d < KH; d += 256) {
        float v = (d < D_) ? (srow[d] - mu) * rs * lng[d] + lnb[d] : 0.f;
        xr[d] = __float2half_rn(v);
    }
}

// --------------------------- fp16 mma.sync GEMM (128x128, 16 warps) --------
// C(half)[M, NP] = A(half)[M, KH] @ Bw(half)[NP, KH]^T + bias(fp32).
// 512 threads, 16 warps in 4x4 grid, warp tile 32x32 (acc = 32 regs),
// 4-stage cp.async, single __syncthreads per K-chunk.
__global__ void __launch_bounds__(GTHR, 1)
gemm_h(const __half* __restrict__ A, const __half* __restrict__ Bw,
       __half* __restrict__ C, const float* __restrict__ bias, int step) {
    const int mt = blockIdx.x / NT_, nt = blockIdx.x % NT_;
    {
        int mtl, cnt;
        if (step < 0) { mtl = mt & 127; cnt = g_cnt[mt >> 7]; }
        else          { mtl = mt;       cnt = g_cnt[step]; }
        if (mtl * TM >= cnt) return;     // inactive m-tile
    }
    extern __shared__ char sm[];
    const uint32_t sb0 = smem_u32(sm);
    const int tid = threadIdx.x;
    const long m0 = (long)mt * TM;
    const int  n0 = nt * TN;

    // cp.async slots: 4 granules (16B) per thread per stage (2 A + 2 B)
    uint32_t sOff[4];
    const __half* gSrc[4];
#pragma unroll
    for (int t = 0; t < 4; ++t) {
        int gi = tid + t * GTHR;           // 0..2047
        int row = gi >> 3, cg = gi & 7;    // row 0..255 (A: 0..127, B: 128..255)
        sOff[t] = row * 128 + ((cg ^ (row & 7)) << 4);
        gSrc[t] = (row < TM) ? (A  + (size_t)(m0 + row) * KH + cg * 8)
                             : (Bw + (size_t)(n0 + row - TM) * KH + cg * 8);
    }

    const int lane = tid & 31, warp = tid >> 5;
    const int mw = (warp & 3) * 32;     // 4 m-warps
    const int nw = (warp >> 2) * 32;    // 4 n-warps
    const int g  = lane >> 2, q = lane & 3;

    uint32_t aRow[2];
#pragma unroll
    for (int i = 0; i < 2; ++i) aRow[i] = mw + i * 16 + (lane & 15);
    const uint32_t aPar = (uint32_t)(lane >> 4);
    uint32_t bRow[2];
#pragma unroll
    for (int jp = 0; jp < 2; ++jp)
        bRow[jp] = nw + jp * 16 + (lane & 7) + ((lane >> 4) << 3);
    const uint32_t bPar = (uint32_t)((lane >> 3) & 1);

    float acc[2][4][4];
#pragma unroll
    for (int i = 0; i < 2; i++)
#pragma unroll
        for (int j = 0; j < 4; j++)
#pragma unroll
            for (int e = 0; e < 4; e++) acc[i][j][e] = 0.f;

    // prologue: chunks 0..2 -> stages 0..2
#pragma unroll
    for (int c = 0; c < NST - 1; ++c) {
        const uint32_t st = sb0 + c * STB;
        const int k0 = c * KCH;
#pragma unroll
        for (int t = 0; t < 4; ++t) cp_async16(st + sOff[t], gSrc[t] + k0);
        CP_COMMIT();
    }

#pragma unroll 1
    for (int c = 0; c < NCHh; ++c) {
        // chunk c resident? outstanding groups at top: c, c+1, c+2
        if (c + 2 < NCHh)       CP_WAIT(2);
        else if (c + 2 == NCHh) CP_WAIT(1);
        else                    CP_WAIT(0);
        __syncthreads();   // all warps see stage c; all done computing c-1

        // prefetch chunk c+3 into stage (c+3)&3 (distinct from c, c+1, c+2)
        if (c + NST - 1 < NCHh) {
            const uint32_t st = sb0 + ((c + NST - 1) & 3) * STB;
            const int k0 = (c + NST - 1) * KCH;
#pragma unroll
            for (int t = 0; t < 4; ++t) cp_async16(st + sOff[t], gSrc[t] + k0);
            CP_COMMIT();
        }

        const uint32_t sA  = sb0 + (c & 3) * STB;
        const uint32_t sBq = sA + TM * 128;
#pragma unroll
        for (int ks = 0; ks < 4; ++ks) {
            uint32_t a[2][4], bf[2][4];
#pragma unroll
            for (int i = 0; i < 2; ++i) {
                uint32_t kg = 2 * ks + aPar;
                ldm4(a[i], sA + aRow[i] * 128 + ((kg ^ (aRow[i] & 7)) << 4));
            }
#pragma unroll
            for (int jp = 0; jp < 2; ++jp) {
                uint32_t kg = 2 * ks + bPar;
                ldm4(bf[jp], sBq + bRow[jp] * 128 + ((kg ^ (bRow[jp] & 7)) << 4));
            }
#pragma unroll
            for (int i = 0; i < 2; ++i)
#pragma unroll
                for (int j = 0; j < 4; ++j)
                    mma_h(acc[i][j], a[i], &bf[j >> 1][(j & 1) * 2]);
        }
    }

    // epilogue: fp32 bias add, store half2
#pragma unroll
    for (int i = 0; i < 2; ++i) {
        const long r0 = m0 + mw + i * 16 + g;
#pragma unroll
        for (int j = 0; j < 4; ++j) {
            const int colg = n0 + nw + j * 8 + 2 * q;
            const float2 bb = *(const float2*)(bias + colg);
            *(__half2*)(C + r0 * NP + colg) =
                __floats2half2_rn(acc[i][j][0] + bb.x, acc[i][j][1] + bb.y);
            *(__half2*)(C + (r0 + 8) * NP + colg) =
                __floats2half2_rn(acc[i][j][2] + bb.x, acc[i][j][3] + bb.y);
        }
    }
}

// --------------------------- GRU cell (permuted rows) ----------------------
__global__ void gru_cell(int t, int first) {
    unsigned i = blockIdx.x * 256u + threadIdx.x;
    if (i >= (unsigned)(B_ * D_)) return;
    int p = i / D_;
    int d = i - p * D_;
    if (p >= g_cnt[t]) return;
    const __half* xg = g_xg + (size_t)t * B_ * NP + (size_t)p * NP;
    float hr, hz, hn, hp;
    if (first) {
        hr = g_bhh[d]; hz = g_bhh[D_ + d]; hn = g_bhh[2 * D_ + d];
        hp = 0.f;
    } else {
        const __half* gh = g_gh + (size_t)p * NP;
        hr = __half2float(gh[d]);
        hz = __half2float(gh[D_ + d]);
        hn = __half2float(gh[2 * D_ + d]);
        hp = __half2float(g_h[(size_t)p * KH + d]);
    }
    float r = 1.f / (1.f + expf(-(__half2float(xg[d])        + hr)));
    float z = 1.f / (1.f + expf(-(__half2float(xg[D_ + d])   + hz)));
    float n = tanhf(__half2float(xg[2 * D_ + d]) + r * hn);
    float hv = (1.f - z) * n + z * hp;
    g_h[(size_t)p * KH + d] = __float2half_rn(hv);
    if (g_sln[p] - 1 == t) g_out[(size_t)p * KD + d] = hv;
}

// --------------------------- batchnorm + folded head -----------------------
__global__ void bn_partial() {
    __shared__ float ss[8][33], sq[8][33];
    int col = blockIdx.x * 32 + threadIdx.x;
    int ty = threadIdx.y;
    float s = 0.f, q = 0.f;
    for (int r = blockIdx.y * 8 + ty; r < B_; r += 256) {
        float v = g_out[(size_t)r * KD + col];
        s += v; q += v * v;
    }
    ss[ty][threadIdx.x] = s; sq[ty][threadIdx.x] = q;
    __syncthreads();
    if (ty == 0) {
        float S = 0.f, Q = 0.f;
#pragma unroll
        for (int k = 0; k < 8; k++) { S += ss[k][threadIdx.x]; Q += sq[k][threadIdx.x]; }
        g_psum[blockIdx.y * KD + col] = S;
        g_psq [blockIdx.y * KD + col] = Q;
    }
}

__global__ void weff_kernel(const float* __restrict__ W2, const float* __restrict__ W1) {
    int gw   = blockIdx.x * 8 + (threadIdx.x >> 5);
    int lane = threadIdx.x & 31;
    if (gw >= 2 * D_) return;
    int o = gw / D_, d = gw - o * D_;
    float acc = 0.f;
    for (int j = lane; j < 2 * D_; j += 32)
        acc += W2[o * (2 * D_) + j] * W1[(size_t)j * D_ + d];
#pragma unroll
    for (int off = 16; off; off >>= 1) acc += __shfl_down_sync(0xffffffffu, acc, off);
    if (lane == 0) g_weff[gw] = acc;
}

__global__ void bn_finalize(const float* __restrict__ bn_g, const float* __restrict__ bn_b) {
    int d = blockIdx.x * 256 + threadIdx.x;
    if (d >= D_) return;
    float s = 0.f, q = 0.f;
#pragma unroll
    for (int p = 0; p < 32; p++) { s += g_psum[p * KD + d]; q += g_psq[p * KD + d]; }
    float mu  = s * (1.f / 16384.f);
    float var = fmaxf(q * (1.f / 16384.f) - mu * mu, 0.f);
    float sc  = bn_g[d] * rsqrtf(var + 1e-4f);
    g_shift[d]    = bn_b[d] - mu * sc;
    g_wbn[d]      = g_weff[d]      * sc;
    g_wbn[KD + d] = g_weff[D_ + d] * sc;
}

__global__ void bbn_kernel(const float* __restrict__ W2, const float* __restrict__ b1,
                           const float* __restrict__ b2) {
    int o = blockIdx.x;
    float acc = 0.f;
    for (int j = threadIdx.x; j < 2 * D_; j += 256) acc += W2[o * (2 * D_) + j] * b1[j];
    for (int d = threadIdx.x; d < D_; d += 256)     acc += g_weff[o * D_ + d] * g_shift[d];
    float2 t = block_reduce2(acc, 0.f);
    if (threadIdx.x == 0) g_bbn[o] = t.x + b2[o];
}

__global__ void logits_kernel(float* __restrict__ out) {
    int gw   = (blockIdx.x * 256 + threadIdx.x) >> 5;
    int lane = threadIdx.x & 31;
    if (gw >= B_) return;
    const float* row = g_out + (size_t)gw * KD;
    float a0 = 0.f, a1 = 0.f;
    for (int d = lane; d < D_; d += 32) {
        float v = row[d];
        a0 += v * g_wbn[d];
        a1 += v * g_wbn[KD + d];
    }
#pragma unroll
    for (int o = 16; o; o >>= 1) {
        a0 += __shfl_down_sync(0xffffffffu, a0, o);
        a1 += __shfl_down_sync(0xffffffffu, a1, o);
    }
    if (lane == 0) {
        int b = g_idx[gw];
        out[2 * b]     = a0 + g_bbn[0];
        out[2 * b + 1] = a1 + g_bbn[1];
    }
}

// --------------------------- launch -----------------------------------------
extern "C" void kernel_launch(void* const* d_in, const int* in_sizes, int n_in,
                              void* d_out, int out_size) {
    const int*   node_seq   = (const int*)d_in[0];
    const int*   fin_seq    = (const int*)d_in[1];
    const int*   nfin_seq   = (const int*)d_in[2];
    const int*   mda_seq    = (const int*)d_in[3];
    const int*   seq_len    = (const int*)d_in[4];
    const float* node_table = (const float*)d_in[5];
    const float* fin_table  = (const float*)d_in[6];
    const float* nfin_table = (const float*)d_in[7];
    const float* bert_table = (const float*)d_in[8];
    const float* ln_g = (const float*)d_in[9];
    const float* ln_b = (const float*)d_in[10];
    const float* W_ih = (const float*)d_in[11];
    const float* W_hh = (const float*)d_in[12];
    const float* b_ih = (const float*)d_in[13];
    const float* b_hh = (const float*)d_in[14];
    const float* bn_g = (const float*)d_in[15];
    const float* bn_b = (const float*)d_in[16];
    const float* W1   = (const float*)d_in[17];
    const float* b1   = (const float*)d_in[18];
    const float* W2   = (const float*)d_in[19];
    const float* b2   = (const float*)d_in[20];

    __half *px, *pxg, *pgh, *ph, *pWih, *pWhh;
    float *pbih, *pbhh;
    cudaGetSymbolAddress((void**)&px,   g_x);
    cudaGetSymbolAddress((void**)&pxg,  g_xg);
    cudaGetSymbolAddress((void**)&pgh,  g_gh);
    cudaGetSymbolAddress((void**)&ph,   g_h);
    cudaGetSymbolAddress((void**)&pWih, g_Wih);
    cudaGetSymbolAddress((void**)&pWhh, g_Whh);
    cudaGetSymbolAddress((void**)&pbih, g_bih);
    cudaGetSymbolAddress((void**)&pbhh, g_bhh);

    cudaFuncSetAttribute(gemm_h, cudaFuncAttributeMaxDynamicSharedMemorySize, SMEMB);

    sort_kernel<<<1, 1024>>>(seq_len);
    pad_weights<<<(NP * KH + 255) / 256, 256>>>(W_ih, W_hh, b_ih, b_hh);
    embed_ln<<<B_ * S_, 256>>>(node_seq, fin_seq, nfin_seq, mda_seq,
                               node_table, fin_table, nfin_table, bert_table,
                               ln_g, ln_b);
    weff_kernel<<<(2 * D_ + 7) / 8, 256>>>(W2, W1);

    // GEMM1: xg = x @ W_ih^T + b_ih  (ragged: per-s active prefix)
    gemm_h<<<(B_ * S_ / TM) * NT_, GTHR, SMEMB>>>(px, pWih, pxg, pbih, -1);

    // GRU: t=0 uses h0=0 => gh = b_hh, no GEMM needed
    gru_cell<<<(B_ * D_ + 255) / 256, 256>>>(0, 1);
    for (int t = 1; t < S_; ++t) {
        gemm_h<<<(B_ / TM) * NT_, GTHR, SMEMB>>>(ph, pWhh, pgh, pbhh, t);
        gru_cell<<<(B_ * D_ + 255) / 256, 256>>>(t, 0);
    }

    // batchnorm stats + folded head
    bn_partial<<<dim3(31, 32), dim3(32, 8)>>>();
    bn_finalize<<<(D_ + 255) / 256, 256>>>(bn_g, bn_b);
    bbn_kernel<<<2, 256>>>(W2, b1, b2);
    logits_kernel<<<(B_ * 32 + 255) / 256, 256>>>((float*)d_out);
}

// round 8
// speedup vs baseline: 1.1456x; 1.1456x over previous
#include <cuda_runtime.h>
#include <cuda_fp16.h>
#include <cstdint>
#include <math.h>

#define B_   16384
#define S_   6
#define D_   991
#define KD   992          // fp32 out-row stride for g_out
#define KH   1024         // padded K for half GEMM operands
#define G3   2973
#define NP   3072         // padded N
#define TM   128
#define TN   128
#define NT_  (NP / TN)    // 24 n-tiles
#define KCH  64           // K halfs per chunk (128 bytes/row)
#define NCHh (KH / KCH)   // 16 chunks
#define NST  3
#define STB  ((TM + TN) * 128)        // 32768 bytes per stage
#define SMEMB (NST * STB)             // 98304

// ------------------- scratch (device globals) ------------------------------
__device__ __half g_x  [(size_t)B_ * S_ * KH];
__device__ __half g_xg [(size_t)S_ * B_ * NP];
__device__ __half g_gh [(size_t)B_ * NP];
__device__ __half g_h  [(size_t)B_ * KH];
__device__ float  g_out[(size_t)B_ * KD];
__device__ __half g_Wih[(size_t)NP * KH];
__device__ __half g_Whh[(size_t)NP * KH];
__device__ float  g_bih[NP];
__device__ float  g_bhh[NP];
__device__ float  g_psum[32 * KD];
__device__ float  g_psq [32 * KD];
__device__ float  g_weff[2 * D_];
__device__ float  g_wbn [2 * KD];
__device__ float  g_shift[KD];
__device__ float  g_bbn [2];
// ragged-batch bookkeeping (permuted row space, sorted by descending seq_len)
__device__ int    g_idx[B_];    // position p -> batch b
__device__ int    g_sln[B_];    // position p -> seq_len
__device__ int    g_cnt[8];     // g_cnt[s] = #rows active at step s (prefix)

// --------------------------- helpers ---------------------------------------
__device__ __forceinline__ uint32_t smem_u32(const void* p) {
    uint32_t a;
    asm("{ .reg .u64 t; cvta.to.shared.u64 t, %1; cvt.u32.u64 %0, t; }" : "=r"(a) : "l"(p));
    return a;
}
__device__ __forceinline__ void cp_async16(uint32_t dst, const void* src) {
    asm volatile("cp.async.cg.shared.global [%0], [%1], 16;" :: "r"(dst), "l"(src) : "memory");
}
#define CP_COMMIT() asm volatile("cp.async.commit_group;" ::: "memory")
#define CP_WAIT(n)  asm volatile("cp.async.wait_group %0;" :: "n"(n) : "memory")

__device__ __forceinline__ void ldm4(uint32_t* r, uint32_t addr) {
    asm volatile("ldmatrix.sync.aligned.m8n8.x4.shared.b16 {%0,%1,%2,%3}, [%4];"
                 : "=r"(r[0]), "=r"(r[1]), "=r"(r[2]), "=r"(r[3]) : "r"(addr));
}
__device__ __forceinline__ void mma_h(float* c, const uint32_t* a, const uint32_t* b) {
    asm volatile(
        "mma.sync.aligned.m16n8k16.row.col.f32.f16.f16.f32 "
        "{%0,%1,%2,%3}, {%4,%5,%6,%7}, {%8,%9}, {%0,%1,%2,%3};"
        : "+f"(c[0]), "+f"(c[1]), "+f"(c[2]), "+f"(c[3])
        : "r"(a[0]), "r"(a[1]), "r"(a[2]), "r"(a[3]), "r"(b[0]), "r"(b[1]));
}

__device__ __forceinline__ float2 block_reduce2(float a, float b) {
    __shared__ float wa[8], wb[8];
    __shared__ float ra, rb;
    int lane = threadIdx.x & 31, w = threadIdx.x >> 5;
#pragma unroll
    for (int o = 16; o; o >>= 1) {
        a += __shfl_down_sync(0xffffffffu, a, o);
        b += __shfl_down_sync(0xffffffffu, b, o);
    }
    if (!lane) { wa[w] = a; wb[w] = b; }
    __syncthreads();
    if (threadIdx.x < 8) { a = wa[threadIdx.x]; b = wb[threadIdx.x]; }
    else { a = 0.f; b = 0.f; }
    if (w == 0) {
#pragma unroll
        for (int o = 4; o; o >>= 1) {
            a += __shfl_down_sync(0xffffffffu, a, o);
            b += __shfl_down_sync(0xffffffffu, b, o);
        }
    }
    if (threadIdx.x == 0) { ra = a; rb = b; }
    __syncthreads();
    return make_float2(ra, rb);
}

// --------------------------- deterministic counting sort --------------------
__global__ void __launch_bounds__(1024)
sort_kernel(const int* __restrict__ seq_len) {
    __shared__ int cnts[1024][6];   // 24 KB
    __shared__ int tot[6], base[6];
    const int tid = threadIdx.x;
    const int b0 = tid * 16;
    int lc[6] = {0, 0, 0, 0, 0, 0};
#pragma unroll
    for (int k = 0; k < 16; ++k) {
        int v = seq_len[b0 + k] - 1;     // 0..5
        lc[v]++;
    }
#pragma unroll
    for (int v = 0; v < 6; ++v) cnts[tid][v] = lc[v];
    __syncthreads();
    if (tid < 6) {
        int run = 0;
        for (int i = 0; i < 1024; ++i) {
            int c = cnts[i][tid];
            cnts[i][tid] = run;
            run += c;
        }
        tot[tid] = run;
    }
    __syncthreads();
    if (tid == 0) {
        int acc = 0;
        for (int v = 5; v >= 0; --v) { base[v] = acc; acc += tot[v]; }
        for (int s = 0; s < 6; ++s) {
            int c = 0;
            for (int v = s; v < 6; ++v) c += tot[v];
            g_cnt[s] = c;
        }
    }
    __syncthreads();
    int off[6];
#pragma unroll
    for (int v = 0; v < 6; ++v) off[v] = base[v] + cnts[tid][v];
#pragma unroll
    for (int k = 0; k < 16; ++k) {
        int b = b0 + k;
        int v = seq_len[b] - 1;
        int p = off[v]++;
        g_idx[p] = b;
        g_sln[p] = v + 1;
    }
}

// --------------------------- init / pack -----------------------------------
__global__ void pad_weights(const float* __restrict__ Wih, const float* __restrict__ Whh,
                            const float* __restrict__ bih, const float* __restrict__ bhh) {
    size_t i = (size_t)blockIdx.x * 256 + threadIdx.x;
    if (i >= (size_t)NP * KH) return;
    int r = (int)(i / KH), c = (int)(i - (size_t)r * KH);
    float vi = 0.f, vh = 0.f;
    if (r < G3 && c < D_) {
        vi = Wih[(size_t)r * D_ + c];
        vh = Whh[(size_t)r * D_ + c];
    }
    g_Wih[i] = __float2half_rn(vi);
    g_Whh[i] = __float2half_rn(vh);
    if (c == 0) {
        g_bih[r] = (r < G3) ? bih[r] : 0.f;
        g_bhh[r] = (r < G3) ? bhh[r] : 0.f;
    }
}

// --------------------------- embed + layernorm (permuted rows) -------------
__global__ void embed_ln(const int* __restrict__ ns, const int* __restrict__ fs,
                         const int* __restrict__ nfs, const int* __restrict__ ms,
                         const float* __restrict__ ntab, const float* __restrict__ ftab,
                         const float* __restrict__ nftab, const float* __restrict__ btab,
                         const float* __restrict__ lng, const float* __restrict__ lnb) {
    const int bid = blockIdx.x;          // row = s*B + p
    const int s = bid >> 14;
    const int p = bid & (B_ - 1);
    if (p >= g_cnt[s]) return;
    const int b = g_idx[p];
    __shared__ float srow[D_];
    const int q = b * S_ + s;
    const int ni = ns[q], fi = fs[q], nfi = nfs[q], mi = ms[q];
    float s1 = 0.f, s2 = 0.f;
    for (int d = threadIdx.x; d < D_; d += 256) {
        float v;
        if (d < 128)      v = ntab[(size_t)ni * 128 + d];
        else if (d < 212) v = ftab[(size_t)fi * 84 + (d - 128)];
        else if (d < 223) v = nftab[(size_t)nfi * 11 + (d - 212)];
        else              v = btab[(size_t)mi * 768 + (d - 223)];
        srow[d] = v;
        s1 += v; s2 += v * v;
    }
    float2 t = block_reduce2(s1, s2);
    const float mu  = t.x * (1.f / 991.f);
    const float var = fmaxf(t.y * (1.f / 991.f) - mu * mu, 0.f);
    const float rs  = rsqrtf(var + 1e-5f);
    __half* xr = g_x + (size_t)bid * KH;
    for (int d = threadIdx.x; d < KH; d += 256) {
        float v = (d < D_) ? (srow[d] - mu) * rs * lng[d] + lnb[d] : 0.f;
        xr[d] = __float2half_rn(v);
    }
}

// --------------------------- fp16 mma.sync GEMM (R5 shape, 1 sync/chunk) ---
// C(half)[M, NP] = A(half)[M, KH] @ Bw(half)[NP, KH]^T + bias(fp32).
// 256 threads, 8 warps (4m x 2n), warp tile 32x64, 3-stage cp.async,
// single __syncthreads per K-chunk (prefetch-after-barrier is race-free).
__global__ void __launch_bounds__(256, 2)
gemm_h(const __half* __restrict__ A, const __half* __restrict__ Bw,
       __half* __restrict__ C, const float* __restrict__ bias, int step) {
    const int mt = blockIdx.x / NT_, nt = blockIdx.x % NT_;
    {
        int mtl, cnt;
        if (step < 0) { mtl = mt & 127; cnt = g_cnt[mt >> 7]; }
        else          { mtl = mt;       cnt = g_cnt[step]; }
        if (mtl * TM >= cnt) return;     // inactive m-tile
    }
    extern __shared__ char sm[];
    const uint32_t sb0 = smem_u32(sm);
    const int tid = threadIdx.x;
    const long m0 = (long)mt * TM;
    const int  n0 = nt * TN;

    // cp.async slots: 4 A granules + 4 B granules (16B each) per thread/stage
    uint32_t aDst[4], bDst[4];
    size_t aOffG[4], bOffG[4];
#pragma unroll
    for (int t = 0; t < 4; ++t) {
        int gidx = tid + t * 256;           // 0..1023
        int row = gidx >> 3, cg = gidx & 7;
        aOffG[t] = (size_t)(m0 + row) * KH + cg * 8;
        bOffG[t] = (size_t)(n0 + row) * KH + cg * 8;
        uint32_t sw = (uint32_t)((cg ^ (row & 7)) << 4);
        aDst[t] = row * 128 + sw;
        bDst[t] = TM * 128 + row * 128 + sw;
    }

    const int lane = tid & 31, warp = tid >> 5;
    const int mw = (warp >> 1) * 32;
    const int nw = (warp & 1) * 64;
    const int g  = lane >> 2, q = lane & 3;

    uint32_t aRow[2];
#pragma unroll
    for (int i = 0; i < 2; ++i) aRow[i] = mw + i * 16 + (lane & 15);
    const uint32_t aPar = (uint32_t)(lane >> 4);
    uint32_t bRow[4];
#pragma unroll
    for (int jp = 0; jp < 4; ++jp)
        bRow[jp] = nw + jp * 16 + (lane & 7) + ((lane >> 4) << 3);
    const uint32_t bPar = (uint32_t)((lane >> 3) & 1);

    float acc[2][8][4];
#pragma unroll
    for (int i = 0; i < 2; i++)
#pragma unroll
        for (int j = 0; j < 8; j++)
#pragma unroll
            for (int e = 0; e < 4; e++) acc[i][j][e] = 0.f;

    // prologue: chunks 0,1 -> stages 0,1
#pragma unroll
    for (int c = 0; c < 2; ++c) {
        const uint32_t st = sb0 + c * STB;
        const int k0 = c * KCH;
#pragma unroll
        for (int t = 0; t < 4; ++t) {
            cp_async16(st + aDst[t], A  + aOffG[t] + k0);
            cp_async16(st + bDst[t], Bw + bOffG[t] + k0);
        }
        CP_COMMIT();
    }

#pragma unroll 1
    for (int c = 0; c < NCHh; ++c) {
        // outstanding groups at top: {c, c+1 (if exists)}
        if (c + 1 < NCHh) CP_WAIT(1);
        else              CP_WAIT(0);
        __syncthreads();   // all warps finished computing c-1 and see stage c

        // prefetch chunk c+2 into stage (c+2)%3 == (c-1)%3 (safe post-barrier)
        if (c + 2 < NCHh) {
            const uint32_t st = sb0 + ((c + 2) % 3) * STB;
            const int k0 = (c + 2) * KCH;
#pragma unroll
            for (int t = 0; t < 4; ++t) {
                cp_async16(st + aDst[t], A  + aOffG[t] + k0);
                cp_async16(st + bDst[t], Bw + bOffG[t] + k0);
            }
            CP_COMMIT();
        }

        const uint32_t sA  = sb0 + (c % 3) * STB;
        const uint32_t sBq = sA + TM * 128;
#pragma unroll
        for (int ks = 0; ks < 4; ++ks) {
            uint32_t a[2][4], bf[4][4];
#pragma unroll
            for (int i = 0; i < 2; ++i) {
                uint32_t kg = 2 * ks + aPar;
                ldm4(a[i], sA + aRow[i] * 128 + ((kg ^ (aRow[i] & 7)) << 4));
            }
#pragma unroll
            for (int jp = 0; jp < 4; ++jp) {
                uint32_t kg = 2 * ks + bPar;
                ldm4(bf[jp], sBq + bRow[jp] * 128 + ((kg ^ (bRow[jp] & 7)) << 4));
            }
#pragma unroll
            for (int i = 0; i < 2; ++i)
#pragma unroll
                for (int j = 0; j < 8; ++j)
                    mma_h(acc[i][j], a[i], &bf[j >> 1][(j & 1) * 2]);
        }
    }

    // epilogue: fp32 bias add, store half2
#pragma unroll
    for (int i = 0; i < 2; ++i) {
        const long r0 = m0 + mw + i * 16 + g;
#pragma unroll
        for (int j = 0; j < 8; ++j) {
            const int colg = n0 + nw + j * 8 + 2 * q;
            const float2 bb = *(const float2*)(bias + colg);
            *(__half2*)(C + r0 * NP + colg) =
                __floats2half2_rn(acc[i][j][0] + bb.x, acc[i][j][1] + bb.y);
            *(__half2*)(C + (r0 + 8) * NP + colg) =
                __floats2half2_rn(acc[i][j][2] + bb.x, acc[i][j][3] + bb.y);
        }
    }
}

// --------------------------- GRU cell (permuted rows) ----------------------
__global__ void __launch_bounds__(1024)
gru_cell(int t, int first) {
    unsigned i = blockIdx.x * 1024u + threadIdx.x;
    if (i >= (unsigned)(B_ * D_)) return;
    int p = i / D_;
    int d = i - p * D_;
    if (p >= g_cnt[t]) return;
    const __half* xg = g_xg + (size_t)t * B_ * NP + (size_t)p * NP;
    float hr, hz, hn, hp;
    if (first) {
        hr = g_bhh[d]; hz = g_bhh[D_ + d]; hn = g_bhh[2 * D_ + d];
        hp = 0.f;
    } else {
        const __half* gh = g_gh + (size_t)p * NP;
        hr = __half2float(gh[d]);
        hz = __half2float(gh[D_ + d]);
        hn = __half2float(gh[2 * D_ + d]);
        hp = __half2float(g_h[(size_t)p * KH + d]);
    }
    float r = 1.f / (1.f + expf(-(__half2float(xg[d])        + hr)));
    float z = 1.f / (1.f + expf(-(__half2float(xg[D_ + d])   + hz)));
    float n = tanhf(__half2float(xg[2 * D_ + d]) + r * hn);
    float hv = (1.f - z) * n + z * hp;
    g_h[(size_t)p * KH + d] = __float2half_rn(hv);
    if (g_sln[p] - 1 == t) g_out[(size_t)p * KD + d] = hv;
}

// --------------------------- batchnorm + folded head -----------------------
__global__ void bn_partial() {
    __shared__ float ss[8][33], sq[8][33];
    int col = blockIdx.x * 32 + threadIdx.x;
    int ty = threadIdx.y;
    float s = 0.f, q = 0.f;
    for (int r = blockIdx.y * 8 + ty; r < B_; r += 256) {
        float v = g_out[(size_t)r * KD + col];
        s += v; q += v * v;
    }
    ss[ty][threadIdx.x] = s; sq[ty][threadIdx.x] = q;
    __syncthreads();
    if (ty == 0) {
        float S = 0.f, Q = 0.f;
#pragma unroll
        for (int k = 0; k < 8; k++) { S += ss[k][threadIdx.x]; Q += sq[k][threadIdx.x]; }
        g_psum[blockIdx.y * KD + col] = S;
        g_psq [blockIdx.y * KD + col] = Q;
    }
}

__global__ void weff_kernel(const float* __restrict__ W2, const float* __restrict__ W1) {
    int gw   = blockIdx.x * 8 + (threadIdx.x >> 5);
    int lane = threadIdx.x & 31;
    if (gw >= 2 * D_) return;
    int o = gw / D_, d = gw - o * D_;
    float acc = 0.f;
    for (int j = lane; j < 2 * D_; j += 32)
        acc += W2[o * (2 * D_) + j] * W1[(size_t)j * D_ + d];
#pragma unroll
    for (int off = 16; off; off >>= 1) acc += __shfl_down_sync(0xffffffffu, acc, off);
    if (lane == 0) g_weff[gw] = acc;
}

__global__ void bn_finalize(const float* __restrict__ bn_g, const float* __restrict__ bn_b) {
    int d = blockIdx.x * 256 + threadIdx.x;
    if (d >= D_) return;
    float s = 0.f, q = 0.f;
#pragma unroll
    for (int p = 0; p < 32; p++) { s += g_psum[p * KD + d]; q += g_psq[p * KD + d]; }
    float mu  = s * (1.f / 16384.f);
    float var = fmaxf(q * (1.f / 16384.f) - mu * mu, 0.f);
    float sc  = bn_g[d] * rsqrtf(var + 1e-4f);
    g_shift[d]    = bn_b[d] - mu * sc;
    g_wbn[d]      = g_weff[d]      * sc;
    g_wbn[KD + d] = g_weff[D_ + d] * sc;
}

__global__ void bbn_kernel(const float* __restrict__ W2, const float* __restrict__ b1,
                           const float* __restrict__ b2) {
    int o = blockIdx.x;
    float acc = 0.f;
    for (int j = threadIdx.x; j < 2 * D_; j += 256) acc += W2[o * (2 * D_) + j] * b1[j];
    for (int d = threadIdx.x; d < D_; d += 256)     acc += g_weff[o * D_ + d] * g_shift[d];
    float2 t = block_reduce2(acc, 0.f);
    if (threadIdx.x == 0) g_bbn[o] = t.x + b2[o];
}

__global__ void logits_kernel(float* __restrict__ out) {
    int gw   = (blockIdx.x * 256 + threadIdx.x) >> 5;
    int lane = threadIdx.x & 31;
    if (gw >= B_) return;
    const float* row = g_out + (size_t)gw * KD;
    float a0 = 0.f, a1 = 0.f;
    for (int d = lane; d < D_; d += 32) {
        float v = row[d];
        a0 += v * g_wbn[d];
        a1 += v * g_wbn[KD + d];
    }
#pragma unroll
    for (int o = 16; o; o >>= 1) {
        a0 += __shfl_down_sync(0xffffffffu, a0, o);
        a1 += __shfl_down_sync(0xffffffffu, a1, o);
    }
    if (lane == 0) {
        int b = g_idx[gw];
        out[2 * b]     = a0 + g_bbn[0];
        out[2 * b + 1] = a1 + g_bbn[1];
    }
}

// --------------------------- launch -----------------------------------------
extern "C" void kernel_launch(void* const* d_in, const int* in_sizes, int n_in,
                              void* d_out, int out_size) {
    const int*   node_seq   = (const int*)d_in[0];
    const int*   fin_seq    = (const int*)d_in[1];
    const int*   nfin_seq   = (const int*)d_in[2];
    const int*   mda_seq    = (const int*)d_in[3];
    const int*   seq_len    = (const int*)d_in[4];
    const float* node_table = (const float*)d_in[5];
    const float* fin_table  = (const float*)d_in[6];
    const float* nfin_table = (const float*)d_in[7];
    const float* bert_table = (const float*)d_in[8];
    const float* ln_g = (const float*)d_in[9];
    const float* ln_b = (const float*)d_in[10];
    const float* W_ih = (const float*)d_in[11];
    const float* W_hh = (const float*)d_in[12];
    const float* b_ih = (const float*)d_in[13];
    const float* b_hh = (const float*)d_in[14];
    const float* bn_g = (const float*)d_in[15];
    const float* bn_b = (const float*)d_in[16];
    const float* W1   = (const float*)d_in[17];
    const float* b1   = (const float*)d_in[18];
    const float* W2   = (const float*)d_in[19];
    const float* b2   = (const float*)d_in[20];

    __half *px, *pxg, *pgh, *ph, *pWih, *pWhh;
    float *pbih, *pbhh;
    cudaGetSymbolAddress((void**)&px,   g_x);
    cudaGetSymbolAddress((void**)&pxg,  g_xg);
    cudaGetSymbolAddress((void**)&pgh,  g_gh);
    cudaGetSymbolAddress((void**)&ph,   g_h);
    cudaGetSymbolAddress((void**)&pWih, g_Wih);
    cudaGetSymbolAddress((void**)&pWhh, g_Whh);
    cudaGetSymbolAddress((void**)&pbih, g_bih);
    cudaGetSymbolAddress((void**)&pbhh, g_bhh);

    cudaFuncSetAttribute(gemm_h, cudaFuncAttributeMaxDynamicSharedMemorySize, SMEMB);

    sort_kernel<<<1, 1024>>>(seq_len);
    pad_weights<<<(NP * KH + 255) / 256, 256>>>(W_ih, W_hh, b_ih, b_hh);
    embed_ln<<<B_ * S_, 256>>>(node_seq, fin_seq, nfin_seq, mda_seq,
                               node_table, fin_table, nfin_table, bert_table,
                               ln_g, ln_b);

    // GEMM1: xg = x @ W_ih^T + b_ih  (ragged: per-s active prefix)
    gemm_h<<<(B_ * S_ / TM) * NT_, 256, SMEMB>>>(px, pWih, pxg, pbih, -1);

    // GRU: t=0 uses h0=0 => gh = b_hh, no GEMM needed
    gru_cell<<<(B_ * D_ + 1023) / 1024, 1024>>>(0, 1);
    for (int t = 1; t < S_; ++t) {
        gemm_h<<<(B_ / TM) * NT_, 256, SMEMB>>>(ph, pWhh, pgh, pbhh, t);
        gru_cell<<<(B_ * D_ + 1023) / 1024, 1024>>>(t, 0);
    }

    // head constant-folding (independent; late so ncu slot catches gemm_h)
    weff_kernel<<<(2 * D_ + 7) / 8, 256>>>(W2, W1);

    // batchnorm stats + folded head
    bn_partial<<<dim3(31, 32), dim3(32, 8)>>>();
    bn_finalize<<<(D_ + 255) / 256, 256>>>(bn_g, bn_b);
    bbn_kernel<<<2, 256>>>(W2, b1, b2);
    logits_kernel<<<(B_ * 32 + 255) / 256, 256>>>((float*)d_out);
}

// round 9
// speedup vs baseline: 1.3446x; 1.1736x over previous
#include <cuda_runtime.h>
#include <cuda_fp16.h>
#include <cstdint>
#include <math.h>

#define B_   16384
#define S_   6
#define D_   991
#define KD   992          // fp32 out-row stride for g_out
#define KH   1024         // padded K for half GEMM operands
#define G3   2973
#define NP   3072         // padded N
#define TM   128
#define TN   128
#define NT_  (NP / TN)    // 24 n-tiles
#define KCH  64           // K halfs per chunk (128 bytes/row)
#define NCHh (KH / KCH)   // 16 chunks
#define NST  3
#define STB  ((TM + TN) * 128)        // 32768 bytes per stage
#define SMEMB (NST * STB)             // 98304

// ------------------- scratch (device globals) ------------------------------
__device__ __half g_x  [(size_t)B_ * S_ * KH];
__device__ __half g_xg [(size_t)S_ * B_ * NP];   // gates at d, 1024+d, 2048+d
__device__ __half g_gh [(size_t)B_ * NP];
__device__ __half g_h  [(size_t)B_ * KH];
__device__ float  g_out[(size_t)B_ * KD];
__device__ __half g_Wih[(size_t)NP * KH];
__device__ __half g_Whh[(size_t)NP * KH];
__device__ float  g_bih[NP];
__device__ float  g_bhh[NP];
__device__ float  g_psum[32 * KD];
__device__ float  g_psq [32 * KD];
__device__ float  g_weff[2 * D_];
__device__ float  g_wbn [2 * KD];
__device__ float  g_shift[KD];
__device__ float  g_bbn [2];
// ragged-batch bookkeeping (permuted row space, sorted by descending seq_len)
__device__ int    g_idx[B_];    // position p -> batch b
__device__ int    g_sln[B_];    // position p -> seq_len
__device__ int    g_cnt[8];     // g_cnt[s] = #rows active at step s (prefix)

// --------------------------- helpers ---------------------------------------
__device__ __forceinline__ uint32_t smem_u32(const void* p) {
    uint32_t a;
    asm("{ .reg .u64 t; cvta.to.shared.u64 t, %1; cvt.u32.u64 %0, t; }" : "=r"(a) : "l"(p));
    return a;
}
__device__ __forceinline__ void cp_async16(uint32_t dst, const void* src) {
    asm volatile("cp.async.cg.shared.global [%0], [%1], 16;" :: "r"(dst), "l"(src) : "memory");
}
#define CP_COMMIT() asm volatile("cp.async.commit_group;" ::: "memory")
#define CP_WAIT(n)  asm volatile("cp.async.wait_group %0;" :: "n"(n) : "memory")

__device__ __forceinline__ void ldm4(uint32_t* r, uint32_t addr) {
    asm volatile("ldmatrix.sync.aligned.m8n8.x4.shared.b16 {%0,%1,%2,%3}, [%4];"
                 : "=r"(r[0]), "=r"(r[1]), "=r"(r[2]), "=r"(r[3]) : "r"(addr));
}
__device__ __forceinline__ void mma_h(float* c, const uint32_t* a, const uint32_t* b) {
    asm volatile(
        "mma.sync.aligned.m16n8k16.row.col.f32.f16.f16.f32 "
        "{%0,%1,%2,%3}, {%4,%5,%6,%7}, {%8,%9}, {%0,%1,%2,%3};"
        : "+f"(c[0]), "+f"(c[1]), "+f"(c[2]), "+f"(c[3])
        : "r"(a[0]), "r"(a[1]), "r"(a[2]), "r"(a[3]), "r"(b[0]), "r"(b[1]));
}

__device__ __forceinline__ float2 block_reduce2(float a, float b) {
    __shared__ float wa[8], wb[8];
    __shared__ float ra, rb;
    int lane = threadIdx.x & 31, w = threadIdx.x >> 5;
#pragma unroll
    for (int o = 16; o; o >>= 1) {
        a += __shfl_down_sync(0xffffffffu, a, o);
        b += __shfl_down_sync(0xffffffffu, b, o);
    }
    if (!lane) { wa[w] = a; wb[w] = b; }
    __syncthreads();
    if (threadIdx.x < 8) { a = wa[threadIdx.x]; b = wb[threadIdx.x]; }
    else { a = 0.f; b = 0.f; }
    if (w == 0) {
#pragma unroll
        for (int o = 4; o; o >>= 1) {
            a += __shfl_down_sync(0xffffffffu, a, o);
            b += __shfl_down_sync(0xffffffffu, b, o);
        }
    }
    if (threadIdx.x == 0) { ra = a; rb = b; }
    __syncthreads();
    return make_float2(ra, rb);
}

// --------------------------- deterministic counting sort --------------------
__global__ void __launch_bounds__(1024)
sort_kernel(const int* __restrict__ seq_len) {
    __shared__ int cnts[1024][6];   // 24 KB
    __shared__ int tot[6], base[6];
    const int tid = threadIdx.x;
    const int b0 = tid * 16;
    int lc[6] = {0, 0, 0, 0, 0, 0};
#pragma unroll
    for (int k = 0; k < 16; ++k) {
        int v = seq_len[b0 + k] - 1;     // 0..5
        lc[v]++;
    }
#pragma unroll
    for (int v = 0; v < 6; ++v) cnts[tid][v] = lc[v];
    __syncthreads();
    if (tid < 6) {
        int run = 0;
        for (int i = 0; i < 1024; ++i) {
            int c = cnts[i][tid];
            cnts[i][tid] = run;
            run += c;
        }
        tot[tid] = run;
    }
    __syncthreads();
    if (tid == 0) {
        int acc = 0;
        for (int v = 5; v >= 0; --v) { base[v] = acc; acc += tot[v]; }
        for (int s = 0; s < 6; ++s) {
            int c = 0;
            for (int v = s; v < 6; ++v) c += tot[v];
            g_cnt[s] = c;
        }
    }
    __syncthreads();
    int off[6];
#pragma unroll
    for (int v = 0; v < 6; ++v) off[v] = base[v] + cnts[tid][v];
#pragma unroll
    for (int k = 0; k < 16; ++k) {
        int b = b0 + k;
        int v = seq_len[b] - 1;
        int p = off[v]++;
        g_idx[p] = b;
        g_sln[p] = v + 1;
    }
}

// --------------------------- init / pack -----------------------------------
// New gate layout: padded row r (0..3071): gate = r>>10, j = r&1023.
// Valid when j < 991; rows 991..1023 of each gate are zero.
__global__ void pad_weights(const float* __restrict__ Wih, const float* __restrict__ Whh,
                            const float* __restrict__ bih, const float* __restrict__ bhh) {
    size_t i = (size_t)blockIdx.x * 256 + threadIdx.x;
    if (i >= (size_t)NP * KH) return;
    int r = (int)(i / KH), c = (int)(i - (size_t)r * KH);
    int gate = r >> 10, j = r & 1023;
    float vi = 0.f, vh = 0.f;
    if (j < D_ && c < D_) {
        size_t src = (size_t)(gate * D_ + j) * D_ + c;
        vi = Wih[src];
        vh = Whh[src];
    }
    g_Wih[i] = __float2half_rn(vi);
    g_Whh[i] = __float2half_rn(vh);
    if (c == 0) {
        g_bih[r] = (j < D_) ? bih[gate * D_ + j] : 0.f;
        g_bhh[r] = (j < D_) ? bhh[gate * D_ + j] : 0.f;
    }
}

// --------------------------- embed + layernorm (permuted rows) -------------
__global__ void embed_ln(const int* __restrict__ ns, const int* __restrict__ fs,
                         const int* __restrict__ nfs, const int* __restrict__ ms,
                         const float* __restrict__ ntab, const float* __restrict__ ftab,
                         const float* __restrict__ nftab, const float* __restrict__ btab,
                         const float* __restrict__ lng, const float* __restrict__ lnb) {
    const int bid = blockIdx.x;          // row = s*B + p
    const int s = bid >> 14;
    const int p = bid & (B_ - 1);
    if (p >= g_cnt[s]) return;
    const int b = g_idx[p];
    __shared__ float srow[D_];
    const int q = b * S_ + s;
    const int ni = ns[q], fi = fs[q], nfi = nfs[q], mi = ms[q];
    float s1 = 0.f, s2 = 0.f;
    for (int d = threadIdx.x; d < D_; d += 256) {
        float v;
        if (d < 128)      v = ntab[(size_t)ni * 128 + d];
        else if (d < 212) v = ftab[(size_t)fi * 84 + (d - 128)];
        else if (d < 223) v = nftab[(size_t)nfi * 11 + (d - 212)];
        else              v = btab[(size_t)mi * 768 + (d - 223)];
        srow[d] = v;
        s1 += v; s2 += v * v;
    }
    float2 t = block_reduce2(s1, s2);
    const float mu  = t.x * (1.f / 991.f);
    const float var = fmaxf(t.y * (1.f / 991.f) - mu * mu, 0.f);
    const float rs  = rsqrtf(var + 1e-5f);
    __half* xr = g_x + (size_t)bid * KH;
    for (int d = threadIdx.x; d < KH; d += 256) {
        float v = (d < D_) ? (srow[d] - mu) * rs * lng[d] + lnb[d] : 0.f;
        xr[d] = __float2half_rn(v);
    }
}

// --------------------------- fp16 mma.sync GEMM (low-reg addressing) -------
// C(half)[M, NP] = A(half)[M, KH] @ Bw(half)[NP, KH]^T + bias(fp32).
// 256 threads, 8 warps (4m x 2n), warp tile 32x64, 3-stage cp.async,
// single __syncthreads per K-chunk. Load addressing collapsed to ~7 regs:
// A/B rows share index pattern; t-steps fold to immediates (+32*KH, +4096).
__global__ void __launch_bounds__(256, 2)
gemm_h(const __half* __restrict__ A, const __half* __restrict__ Bw,
       __half* __restrict__ C, const float* __restrict__ bias, int step) {
    const int mt = blockIdx.x / NT_, nt = blockIdx.x % NT_;
    {
        int mtl, cnt;
        if (step < 0) { mtl = mt & 127; cnt = g_cnt[mt >> 7]; }
        else          { mtl = mt;       cnt = g_cnt[step]; }
        if (mtl * TM >= cnt) return;     // inactive m-tile
    }
    extern __shared__ char sm[];
    const uint32_t sb0 = smem_u32(sm);
    const int tid = threadIdx.x;

    // tile base pointers (global)
    const __half* Ab = A  + (size_t)mt * TM * KH;
    const __half* Bb = Bw + (size_t)nt * TN * KH;

    // collapsed cp.async addressing: one row offset + one smem offset
    const int row0 = tid >> 3;                       // 0..31
    const int cg   = tid & 7;
    const uint32_t rowOff0 = (uint32_t)row0 * KH + (uint32_t)cg * 8;    // elements
    const uint32_t dst0    = (uint32_t)row0 * 128 + (uint32_t)((cg ^ (row0 & 7)) << 4);

#define PREF(stagebase, k0_) do {                                            \
    _Pragma("unroll")                                                        \
    for (int t_ = 0; t_ < 4; ++t_) {                                         \
        cp_async16((stagebase) + dst0 + t_ * 4096,                           \
                   Ab + rowOff0 + (uint32_t)t_ * 32 * KH + (k0_));           \
        cp_async16((stagebase) + (TM * 128) + dst0 + t_ * 4096,              \
                   Bb + rowOff0 + (uint32_t)t_ * 32 * KH + (k0_));           \
    }                                                                        \
    CP_COMMIT();                                                             \
} while (0)

    const int lane = tid & 31, warp = tid >> 5;
    const int mw = (warp >> 1) * 32;
    const int nw = (warp & 1) * 64;
    const int g  = lane >> 2, q = lane & 3;

    // ldmatrix addressing precomputed as byte offsets (kept minimal)
    uint32_t aRB[2];
#pragma unroll
    for (int i = 0; i < 2; ++i) aRB[i] = (uint32_t)(mw + i * 16 + (lane & 15)) * 128;
    const uint32_t aSw = (uint32_t)((mw + (lane & 15)) & 7);   // row&7 invariant in i (16-step)
    const uint32_t aPar = (uint32_t)(lane >> 4);
    uint32_t bRB[4];
    uint32_t bSw[4];
#pragma unroll
    for (int jp = 0; jp < 4; ++jp) {
        uint32_t br = (uint32_t)(nw + jp * 16 + (lane & 7) + ((lane >> 4) << 3));
        bRB[jp] = br * 128;
        bSw[jp] = br & 7;
    }
    const uint32_t bPar = (uint32_t)((lane >> 3) & 1);

    float acc[2][8][4];
#pragma unroll
    for (int i = 0; i < 2; i++)
#pragma unroll
        for (int j = 0; j < 8; j++)
#pragma unroll
            for (int e = 0; e < 4; e++) acc[i][j][e] = 0.f;

    // prologue: chunks 0,1 -> stages 0,1
    PREF(sb0, 0);
    PREF(sb0 + STB, KCH);

#pragma unroll 1
    for (int c = 0; c < NCHh; ++c) {
        if (c + 1 < NCHh) CP_WAIT(1);
        else              CP_WAIT(0);
        __syncthreads();   // all warps finished computing c-1 and see stage c

        if (c + 2 < NCHh) {
            PREF(sb0 + ((c + 2) % 3) * STB, (uint32_t)(c + 2) * KCH);
        }

        const uint32_t sA  = sb0 + (c % 3) * STB;
        const uint32_t sBq = sA + TM * 128;
#pragma unroll
        for (int ks = 0; ks < 4; ++ks) {
            uint32_t a[2][4], bf[4][4];
#pragma unroll
            for (int i = 0; i < 2; ++i) {
                uint32_t kg = 2 * ks + aPar;
                ldm4(a[i], sA + aRB[i] + ((kg ^ aSw) << 4));
            }
#pragma unroll
            for (int jp = 0; jp < 4; ++jp) {
                uint32_t kg = 2 * ks + bPar;
                ldm4(bf[jp], sBq + bRB[jp] + ((kg ^ bSw[jp]) << 4));
            }
#pragma unroll
            for (int i = 0; i < 2; ++i)
#pragma unroll
                for (int j = 0; j < 8; ++j)
                    mma_h(acc[i][j], a[i], &bf[j >> 1][(j & 1) * 2]);
        }
    }
#undef PREF

    // epilogue: fp32 bias add, store half2
    const long m0 = (long)mt * TM;
    const int  n0 = nt * TN;
#pragma unroll
    for (int i = 0; i < 2; ++i) {
        const long r0 = m0 + mw + i * 16 + g;
#pragma unroll
        for (int j = 0; j < 8; ++j) {
            const int colg = n0 + nw + j * 8 + 2 * q;
            const float2 bb = *(const float2*)(bias + colg);
            *(__half2*)(C + r0 * NP + colg) =
                __floats2half2_rn(acc[i][j][0] + bb.x, acc[i][j][1] + bb.y);
            *(__half2*)(C + (r0 + 8) * NP + colg) =
                __floats2half2_rn(acc[i][j][2] + bb.x, acc[i][j][3] + bb.y);
        }
    }
}

// --------------------------- GRU cell (permuted rows, half2) ---------------
// Gates at padded offsets d, 1024+d, 2048+d. Processes 2 d's per thread.
__global__ void __launch_bounds__(1024)
gru_cell(int t, int first) {
    unsigned i = blockIdx.x * 1024u + threadIdx.x;
    if (i >= (unsigned)(B_ * 496)) return;
    int p = i / 496;
    int j = i - p * 496;              // half2 index, d = 2j (0..990)
    if (p >= g_cnt[t]) return;
    const int dd = j * 2;
    const __half2* xg = (const __half2*)(g_xg + (size_t)t * B_ * NP + (size_t)p * NP);
    float2 xr = __half22float2(xg[j]);
    float2 xz = __half22float2(xg[512 + j]);
    float2 xn = __half22float2(xg[1024 + j]);
    float2 hr, hz, hn, hp;
    if (first) {
        hr = *(const float2*)(g_bhh + dd);
        hz = *(const float2*)(g_bhh + 1024 + dd);
        hn = *(const float2*)(g_bhh + 2048 + dd);
        hp = make_float2(0.f, 0.f);
    } else {
        const __half2* gh = (const __half2*)(g_gh + (size_t)p * NP);
        hr = __half22float2(gh[j]);
        hz = __half22float2(gh[512 + j]);
        hn = __half22float2(gh[1024 + j]);
        hp = __half22float2(*(const __half2*)(g_h + (size_t)p * KH + dd));
    }
    float r0 = 1.f / (1.f + expf(-(xr.x + hr.x)));
    float r1 = 1.f / (1.f + expf(-(xr.y + hr.y)));
    float z0 = 1.f / (1.f + expf(-(xz.x + hz.x)));
    float z1 = 1.f / (1.f + expf(-(xz.y + hz.y)));
    float n0 = tanhf(xn.x + r0 * hn.x);
    float n1 = tanhf(xn.y + r1 * hn.y);
    float h0 = (1.f - z0) * n0 + z0 * hp.x;
    float h1 = (1.f - z1) * n1 + z1 * hp.y;
    *(__half2*)(g_h + (size_t)p * KH + dd) = __floats2half2_rn(h0, h1);
    if (g_sln[p] - 1 == t) {
        float* orow = g_out + (size_t)p * KD;
        orow[dd]     = h0;
        orow[dd + 1] = h1;   // dd+1 <= 991 < KD; col 991 unused by logits
    }
}

// --------------------------- batchnorm + folded head -----------------------
__global__ void bn_partial() {
    __shared__ float ss[8][33], sq[8][33];
    int col = blockIdx.x * 32 + threadIdx.x;
    int ty = threadIdx.y;
    float s = 0.f, q = 0.f;
    for (int r = blockIdx.y * 8 + ty; r < B_; r += 256) {
        float v = g_out[(size_t)r * KD + col];
        s += v; q += v * v;
    }
    ss[ty][threadIdx.x] = s; sq[ty][threadIdx.x] = q;
    __syncthreads();
    if (ty == 0) {
        float S = 0.f, Q = 0.f;
#pragma unroll
        for (int k = 0; k < 8; k++) { S += ss[k][threadIdx.x]; Q += sq[k][threadIdx.x]; }
        g_psum[blockIdx.y * KD + col] = S;
        g_psq [blockIdx.y * KD + col] = Q;
    }
}

__global__ void weff_kernel(const float* __restrict__ W2, const float* __restrict__ W1) {
    int gw   = blockIdx.x * 8 + (threadIdx.x >> 5);
    int lane = threadIdx.x & 31;
    if (gw >= 2 * D_) return;
    int o = gw / D_, d = gw - o * D_;
    float acc = 0.f;
    for (int j = lane; j < 2 * D_; j += 32)
        acc += W2[o * (2 * D_) + j] * W1[(size_t)j * D_ + d];
#pragma unroll
    for (int off = 16; off; off >>= 1) acc += __shfl_down_sync(0xffffffffu, acc, off);
    if (lane == 0) g_weff[gw] = acc;
}

__global__ void bn_finalize(const float* __restrict__ bn_g, const float* __restrict__ bn_b) {
    int d = blockIdx.x * 256 + threadIdx.x;
    if (d >= D_) return;
    float s = 0.f, q = 0.f;
#pragma unroll
    for (int p = 0; p < 32; p++) { s += g_psum[p * KD + d]; q += g_psq[p * KD + d]; }
    float mu  = s * (1.f / 16384.f);
    float var = fmaxf(q * (1.f / 16384.f) - mu * mu, 0.f);
    float sc  = bn_g[d] * rsqrtf(var + 1e-4f);
    g_shift[d]    = bn_b[d] - mu * sc;
    g_wbn[d]      = g_weff[d]      * sc;
    g_wbn[KD + d] = g_weff[D_ + d] * sc;
}

__global__ void bbn_kernel(const float* __restrict__ W2, const float* __restrict__ b1,
                           const float* __restrict__ b2) {
    int o = blockIdx.x;
    float acc = 0.f;
    for (int j = threadIdx.x; j < 2 * D_; j += 256) acc += W2[o * (2 * D_) + j] * b1[j];
    for (int d = threadIdx.x; d < D_; d += 256)     acc += g_weff[o * D_ + d] * g_shift[d];
    float2 t = block_reduce2(acc, 0.f);
    if (threadIdx.x == 0) g_bbn[o] = t.x + b2[o];
}

__global__ void logits_kernel(float* __restrict__ out) {
    int gw   = (blockIdx.x * 256 + threadIdx.x) >> 5;
    int lane = threadIdx.x & 31;
    if (gw >= B_) return;
    const float* row = g_out + (size_t)gw * KD;
    float a0 = 0.f, a1 = 0.f;
    for (int d = lane; d < D_; d += 32) {
        float v = row[d];
        a0 += v * g_wbn[d];
        a1 += v * g_wbn[KD + d];
    }
#pragma unroll
    for (int o = 16; o; o >>= 1) {
        a0 += __shfl_down_sync(0xffffffffu, a0, o);
        a1 += __shfl_down_sync(0xffffffffu, a1, o);
    }
    if (lane == 0) {
        int b = g_idx[gw];
        out[2 * b]     = a0 + g_bbn[0];
        out[2 * b + 1] = a1 + g_bbn[1];
    }
}

// --------------------------- launch -----------------------------------------
extern "C" void kernel_launch(void* const* d_in, const int* in_sizes, int n_in,
                              void* d_out, int out_size) {
    const int*   node_seq   = (const int*)d_in[0];
    const int*   fin_seq    = (const int*)d_in[1];
    const int*   nfin_seq   = (const int*)d_in[2];
    const int*   mda_seq    = (const int*)d_in[3];
    const int*   seq_len    = (const int*)d_in[4];
    const float* node_table = (const float*)d_in[5];
    const float* fin_table  = (const float*)d_in[6];
    const float* nfin_table = (const float*)d_in[7];
    const float* bert_table = (const float*)d_in[8];
    const float* ln_g = (const float*)d_in[9];
    const float* ln_b = (const float*)d_in[10];
    const float* W_ih = (const float*)d_in[11];
    const float* W_hh = (const float*)d_in[12];
    const float* b_ih = (const float*)d_in[13];
    const float* b_hh = (const float*)d_in[14];
    const float* bn_g = (const float*)d_in[15];
    const float* bn_b = (const float*)d_in[16];
    const float* W1   = (const float*)d_in[17];
    const float* b1   = (const float*)d_in[18];
    const float* W2   = (const float*)d_in[19];
    const float* b2   = (const float*)d_in[20];

    __half *px, *pxg, *pgh, *ph, *pWih, *pWhh;
    float *pbih, *pbhh;
    cudaGetSymbolAddress((void**)&px,   g_x);
    cudaGetSymbolAddress((void**)&pxg,  g_xg);
    cudaGetSymbolAddress((void**)&pgh,  g_gh);
    cudaGetSymbolAddress((void**)&ph,   g_h);
    cudaGetSymbolAddress((void**)&pWih, g_Wih);
    cudaGetSymbolAddress((void**)&pWhh, g_Whh);
    cudaGetSymbolAddress((void**)&pbih, g_bih);
    cudaGetSymbolAddress((void**)&pbhh, g_bhh);

    cudaFuncSetAttribute(gemm_h, cudaFuncAttributeMaxDynamicSharedMemorySize, SMEMB);

    sort_kernel<<<1, 1024>>>(seq_len);
    pad_weights<<<(NP * KH + 255) / 256, 256>>>(W_ih, W_hh, b_ih, b_hh);
    embed_ln<<<B_ * S_, 256>>>(node_seq, fin_seq, nfin_seq, mda_seq,
                               node_table, fin_table, nfin_table, bert_table,
                               ln_g, ln_b);

    // GEMM1: xg = x @ W_ih^T + b_ih  (ragged: per-s active prefix)
    gemm_h<<<(B_ * S_ / TM) * NT_, 256, SMEMB>>>(px, pWih, pxg, pbih, -1);

    // GRU: t=0 uses h0=0 => gh = b_hh, no GEMM needed
    gru_cell<<<(B_ * 496 + 1023) / 1024, 1024>>>(0, 1);
    for (int t = 1; t < S_; ++t) {
        gemm_h<<<(B_ / TM) * NT_, 256, SMEMB>>>(ph, pWhh, pgh, pbhh, t);
        gru_cell<<<(B_ * 496 + 1023) / 1024, 1024>>>(t, 0);
    }

    // head constant-folding (independent; late so ncu slot catches gemm_h)
    weff_kernel<<<(2 * D_ + 7) / 8, 256>>>(W2, W1);

    // batchnorm stats + folded head
    bn_partial<<<dim3(31, 32), dim3(32, 8)>>>();
    bn_finalize<<<(D_ + 255) / 256, 256>>>(bn_g, bn_b);
    bbn_kernel<<<2, 256>>>(W2, b1, b2);
    logits_kernel<<<(B_ * 32 + 255) / 256, 256>>>((float*)d_out);
}

// round 10
// speedup vs baseline: 1.3772x; 1.0243x over previous
#include <cuda_runtime.h>
#include <cuda_fp16.h>
#include <cstdint>
#include <math.h>

#define B_   16384
#define S_   6
#define D_   991
#define KD   992          // fp32 out-row stride for g_out
#define KH   1024         // padded K for half GEMM operands
#define G3   2973
#define NP   3072         // padded N
#define TM   128
#define TN   128
#define NT_  (NP / TN)    // 24 n-tiles
#define KCH  64           // K halfs per chunk (128 bytes/row)
#define NCHh (KH / KCH)   // 16 chunks
#define NST  3
#define STB  ((TM + TN) * 128)        // 32768 bytes per stage
#define SMEMB (NST * STB)             // 98304

// ------------------- scratch (device globals) ------------------------------
__device__ __half g_x  [(size_t)B_ * S_ * KH];
__device__ __half g_xg [(size_t)S_ * B_ * NP];   // gates at d, 1024+d, 2048+d
__device__ __half g_gh [(size_t)B_ * NP];
__device__ __half g_h  [(size_t)B_ * KH];
__device__ float  g_out[(size_t)B_ * KD];
__device__ __half g_Wih[(size_t)NP * KH];
__device__ __half g_Whh[(size_t)NP * KH];
__device__ float  g_bih[NP];
__device__ float  g_bhh[NP];
__device__ float  g_psum[32 * KD];
__device__ float  g_psq [32 * KD];
__device__ float  g_weff[2 * D_];
__device__ float  g_wbn [2 * KD];
__device__ float  g_shift[KD];
__device__ float  g_bbn [2];
// ragged-batch bookkeeping (permuted row space, sorted by descending seq_len)
__device__ int    g_idx[B_];    // position p -> batch b
__device__ int    g_sln[B_];    // position p -> seq_len
__device__ int    g_cnt[8];     // g_cnt[s] = #rows active at step s (prefix)

// --------------------------- helpers ---------------------------------------
__device__ __forceinline__ uint32_t smem_u32(const void* p) {
    uint32_t a;
    asm("{ .reg .u64 t; cvta.to.shared.u64 t, %1; cvt.u32.u64 %0, t; }" : "=r"(a) : "l"(p));
    return a;
}
__device__ __forceinline__ void cp_async16(uint32_t dst, const void* src) {
    asm volatile("cp.async.cg.shared.global [%0], [%1], 16;" :: "r"(dst), "l"(src) : "memory");
}
#define CP_COMMIT() asm volatile("cp.async.commit_group;" ::: "memory")
#define CP_WAIT(n)  asm volatile("cp.async.wait_group %0;" :: "n"(n) : "memory")

__device__ __forceinline__ void ldm4(uint32_t* r, uint32_t addr) {
    asm volatile("ldmatrix.sync.aligned.m8n8.x4.shared.b16 {%0,%1,%2,%3}, [%4];"
                 : "=r"(r[0]), "=r"(r[1]), "=r"(r[2]), "=r"(r[3]) : "r"(addr));
}
__device__ __forceinline__ void mma_h(float* c, const uint32_t* a, const uint32_t* b) {
    asm volatile(
        "mma.sync.aligned.m16n8k16.row.col.f32.f16.f16.f32 "
        "{%0,%1,%2,%3}, {%4,%5,%6,%7}, {%8,%9}, {%0,%1,%2,%3};"
        : "+f"(c[0]), "+f"(c[1]), "+f"(c[2]), "+f"(c[3])
        : "r"(a[0]), "r"(a[1]), "r"(a[2]), "r"(a[3]), "r"(b[0]), "r"(b[1]));
}

__device__ __forceinline__ float2 block_reduce2(float a, float b) {
    __shared__ float wa[8], wb[8];
    __shared__ float ra, rb;
    int lane = threadIdx.x & 31, w = threadIdx.x >> 5;
#pragma unroll
    for (int o = 16; o; o >>= 1) {
        a += __shfl_down_sync(0xffffffffu, a, o);
        b += __shfl_down_sync(0xffffffffu, b, o);
    }
    if (!lane) { wa[w] = a; wb[w] = b; }
    __syncthreads();
    if (threadIdx.x < 8) { a = wa[threadIdx.x]; b = wb[threadIdx.x]; }
    else { a = 0.f; b = 0.f; }
    if (w == 0) {
#pragma unroll
        for (int o = 4; o; o >>= 1) {
            a += __shfl_down_sync(0xffffffffu, a, o);
            b += __shfl_down_sync(0xffffffffu, b, o);
        }
    }
    if (threadIdx.x == 0) { ra = a; rb = b; }
    __syncthreads();
    return make_float2(ra, rb);
}

// --------------------------- deterministic counting sort --------------------
__global__ void __launch_bounds__(1024)
sort_kernel(const int* __restrict__ seq_len) {
    __shared__ int cnts[1024][6];   // 24 KB
    __shared__ int tot[6], base[6];
    const int tid = threadIdx.x;
    const int b0 = tid * 16;
    int lc[6] = {0, 0, 0, 0, 0, 0};
#pragma unroll
    for (int k = 0; k < 16; ++k) {
        int v = seq_len[b0 + k] - 1;     // 0..5
        lc[v]++;
    }
#pragma unroll
    for (int v = 0; v < 6; ++v) cnts[tid][v] = lc[v];
    __syncthreads();
    if (tid < 6) {
        int run = 0;
        for (int i = 0; i < 1024; ++i) {
            int c = cnts[i][tid];
            cnts[i][tid] = run;
            run += c;
        }
        tot[tid] = run;
    }
    __syncthreads();
    if (tid == 0) {
        int acc = 0;
        for (int v = 5; v >= 0; --v) { base[v] = acc; acc += tot[v]; }
        for (int s = 0; s < 6; ++s) {
            int c = 0;
            for (int v = s; v < 6; ++v) c += tot[v];
            g_cnt[s] = c;
        }
    }
    __syncthreads();
    int off[6];
#pragma unroll
    for (int v = 0; v < 6; ++v) off[v] = base[v] + cnts[tid][v];
#pragma unroll
    for (int k = 0; k < 16; ++k) {
        int b = b0 + k;
        int v = seq_len[b] - 1;
        int p = off[v]++;
        g_idx[p] = b;
        g_sln[p] = v + 1;
    }
}

// --------------------------- init / pack -----------------------------------
// Gate layout: padded row r (0..3071): gate = r>>10, j = r&1023.
__global__ void pad_weights(const float* __restrict__ Wih, const float* __restrict__ Whh,
                            const float* __restrict__ bih, const float* __restrict__ bhh) {
    size_t i = (size_t)blockIdx.x * 256 + threadIdx.x;
    if (i >= (size_t)NP * KH) return;
    int r = (int)(i / KH), c = (int)(i - (size_t)r * KH);
    int gate = r >> 10, j = r & 1023;
    float vi = 0.f, vh = 0.f;
    if (j < D_ && c < D_) {
        size_t src = (size_t)(gate * D_ + j) * D_ + c;
        vi = Wih[src];
        vh = Whh[src];
    }
    g_Wih[i] = __float2half_rn(vi);
    g_Whh[i] = __float2half_rn(vh);
    if (c == 0) {
        g_bih[r] = (j < D_) ? bih[gate * D_ + j] : 0.f;
        g_bhh[r] = (j < D_) ? bhh[gate * D_ + j] : 0.f;
    }
}

// --------------------------- embed + layernorm (permuted rows) -------------
__global__ void embed_ln(const int* __restrict__ ns, const int* __restrict__ fs,
                         const int* __restrict__ nfs, const int* __restrict__ ms,
                         const float* __restrict__ ntab, const float* __restrict__ ftab,
                         const float* __restrict__ nftab, const float* __restrict__ btab,
                         const float* __restrict__ lng, const float* __restrict__ lnb) {
    const int bid = blockIdx.x;          // row = s*B + p
    const int s = bid >> 14;
    const int p = bid & (B_ - 1);
    if (p >= g_cnt[s]) return;
    const int b = g_idx[p];
    __shared__ float srow[D_];
    const int q = b * S_ + s;
    const int ni = ns[q], fi = fs[q], nfi = nfs[q], mi = ms[q];
    float s1 = 0.f, s2 = 0.f;
    for (int d = threadIdx.x; d < D_; d += 256) {
        float v;
        if (d < 128)      v = ntab[(size_t)ni * 128 + d];
        else if (d < 212) v = ftab[(size_t)fi * 84 + (d - 128)];
        else if (d < 223) v = nftab[(size_t)nfi * 11 + (d - 212)];
        else              v = btab[(size_t)mi * 768 + (d - 223)];
        srow[d] = v;
        s1 += v; s2 += v * v;
    }
    float2 t = block_reduce2(s1, s2);
    const float mu  = t.x * (1.f / 991.f);
    const float var = fmaxf(t.y * (1.f / 991.f) - mu * mu, 0.f);
    const float rs  = rsqrtf(var + 1e-5f);
    __half* xr = g_x + (size_t)bid * KH;
    for (int d = threadIdx.x; d < KH; d += 256) {
        float v = (d < D_) ? (srow[d] - mu) * rs * lng[d] + lnb[d] : 0.f;
        xr[d] = __float2half_rn(v);
    }
}

// --------------------------- fp16 mma.sync GEMM ----------------------------
// C(half)[M, NP] = A(half)[M, KH] @ Bw(half)[NP, KH]^T + bias(fp32).
// 256 threads, 8 warps (4m x 2n), warp tile 32x64, 3-stage cp.async,
// single __syncthreads per K-chunk. Inner loop: A-frag double buffer across
// ks, B-frag loaded per-jp and consumed immediately -> steady LDSM:MMA mix.
__global__ void __launch_bounds__(256, 2)
gemm_h(const __half* __restrict__ A, const __half* __restrict__ Bw,
       __half* __restrict__ C, const float* __restrict__ bias, int step) {
    const int mt = blockIdx.x / NT_, nt = blockIdx.x % NT_;
    {
        int mtl, cnt;
        if (step < 0) { mtl = mt & 127; cnt = g_cnt[mt >> 7]; }
        else          { mtl = mt;       cnt = g_cnt[step]; }
        if (mtl * TM >= cnt) return;     // inactive m-tile
    }
    extern __shared__ char sm[];
    const uint32_t sb0 = smem_u32(sm);
    const int tid = threadIdx.x;

    // tile base pointers (global)
    const __half* Ab = A  + (size_t)mt * TM * KH;
    const __half* Bb = Bw + (size_t)nt * TN * KH;

    // collapsed cp.async addressing: one row offset + one smem offset
    const int row0 = tid >> 3;                       // 0..31
    const int cg   = tid & 7;
    const uint32_t rowOff0 = (uint32_t)row0 * KH + (uint32_t)cg * 8;    // elements
    const uint32_t dst0    = (uint32_t)row0 * 128 + (uint32_t)((cg ^ (row0 & 7)) << 4);

#define PREF(stagebase, k0_) do {                                            \
    _Pragma("unroll")                                                        \
    for (int t_ = 0; t_ < 4; ++t_) {                                         \
        cp_async16((stagebase) + dst0 + t_ * 4096,                           \
                   Ab + rowOff0 + (uint32_t)t_ * 32 * KH + (k0_));           \
        cp_async16((stagebase) + (TM * 128) + dst0 + t_ * 4096,              \
                   Bb + rowOff0 + (uint32_t)t_ * 32 * KH + (k0_));           \
    }                                                                        \
    CP_COMMIT();                                                             \
} while (0)

    const int lane = tid & 31, warp = tid >> 5;
    const int mw = (warp >> 1) * 32;
    const int nw = (warp & 1) * 64;
    const int g  = lane >> 2, q = lane & 3;

    // ldmatrix addressing precomputed as byte offsets
    uint32_t aRB[2];
#pragma unroll
    for (int i = 0; i < 2; ++i) aRB[i] = (uint32_t)(mw + i * 16 + (lane & 15)) * 128;
    const uint32_t aSw = (uint32_t)((mw + (lane & 15)) & 7);
    const uint32_t aPar = (uint32_t)(lane >> 4);
    uint32_t bRB[4];
    uint32_t bSw[4];
#pragma unroll
    for (int jp = 0; jp < 4; ++jp) {
        uint32_t br = (uint32_t)(nw + jp * 16 + (lane & 7) + ((lane >> 4) << 3));
        bRB[jp] = br * 128;
        bSw[jp] = br & 7;
    }
    const uint32_t bPar = (uint32_t)((lane >> 3) & 1);

    float acc[2][8][4];
#pragma unroll
    for (int i = 0; i < 2; i++)
#pragma unroll
        for (int j = 0; j < 8; j++)
#pragma unroll
            for (int e = 0; e < 4; e++) acc[i][j][e] = 0.f;

    // prologue: chunks 0,1 -> stages 0,1
    PREF(sb0, 0);
    PREF(sb0 + STB, KCH);

#pragma unroll 1
    for (int c = 0; c < NCHh; ++c) {
        if (c + 1 < NCHh) CP_WAIT(1);
        else              CP_WAIT(0);
        __syncthreads();   // all warps finished computing c-1 and see stage c

        if (c + 2 < NCHh) {
            PREF(sb0 + ((c + 2) % 3) * STB, (uint32_t)(c + 2) * KCH);
        }

        const uint32_t sA  = sb0 + (c % 3) * STB;
        const uint32_t sBq = sA + TM * 128;

        // A fragments for ks=0
        uint32_t a0[4], a1[4];
        {
            uint32_t kg = aPar;
            ldm4(a0, sA + aRB[0] + ((kg ^ aSw) << 4));
            ldm4(a1, sA + aRB[1] + ((kg ^ aSw) << 4));
        }
#pragma unroll
        for (int ks = 0; ks < 4; ++ks) {
            uint32_t an0[4], an1[4];
            if (ks < 3) {   // prefetch A for ks+1 (double buffer)
                uint32_t kg = 2 * (ks + 1) + aPar;
                ldm4(an0, sA + aRB[0] + ((kg ^ aSw) << 4));
                ldm4(an1, sA + aRB[1] + ((kg ^ aSw) << 4));
            }
#pragma unroll
            for (int jp = 0; jp < 4; ++jp) {
                uint32_t bf[4];
                uint32_t kg = 2 * ks + bPar;
                ldm4(bf, sBq + bRB[jp] + ((kg ^ bSw[jp]) << 4));
                mma_h(acc[0][2 * jp],     a0, bf);
                mma_h(acc[0][2 * jp + 1], a0, bf + 2);
                mma_h(acc[1][2 * jp],     a1, bf);
                mma_h(acc[1][2 * jp + 1], a1, bf + 2);
            }
            if (ks < 3) {
#pragma unroll
                for (int e = 0; e < 4; ++e) { a0[e] = an0[e]; a1[e] = an1[e]; }
            }
        }
    }
#undef PREF

    // epilogue: fp32 bias add, store half2
    const long m0 = (long)mt * TM;
    const int  n0 = nt * TN;
#pragma unroll
    for (int i = 0; i < 2; ++i) {
        const long r0 = m0 + mw + i * 16 + g;
#pragma unroll
        for (int j = 0; j < 8; ++j) {
            const int colg = n0 + nw + j * 8 + 2 * q;
            const float2 bb = *(const float2*)(bias + colg);
            *(__half2*)(C + r0 * NP + colg) =
                __floats2half2_rn(acc[i][j][0] + bb.x, acc[i][j][1] + bb.y);
            *(__half2*)(C + (r0 + 8) * NP + colg) =
                __floats2half2_rn(acc[i][j][2] + bb.x, acc[i][j][3] + bb.y);
        }
    }
}

// --------------------------- GRU cell (permuted rows, half2) ---------------
__global__ void __launch_bounds__(1024)
gru_cell(int t, int first) {
    unsigned i = blockIdx.x * 1024u + threadIdx.x;
    if (i >= (unsigned)(B_ * 496)) return;
    int p = i / 496;
    int j = i - p * 496;              // half2 index, d = 2j (0..990)
    if (p >= g_cnt[t]) return;
    const int dd = j * 2;
    const __half2* xg = (const __half2*)(g_xg + (size_t)t * B_ * NP + (size_t)p * NP);
    float2 xr = __half22float2(xg[j]);
    float2 xz = __half22float2(xg[512 + j]);
    float2 xn = __half22float2(xg[1024 + j]);
    float2 hr, hz, hn, hp;
    if (first) {
        hr = *(const float2*)(g_bhh + dd);
        hz = *(const float2*)(g_bhh + 1024 + dd);
        hn = *(const float2*)(g_bhh + 2048 + dd);
        hp = make_float2(0.f, 0.f);
    } else {
        const __half2* gh = (const __half2*)(g_gh + (size_t)p * NP);
        hr = __half22float2(gh[j]);
        hz = __half22float2(gh[512 + j]);
        hn = __half22float2(gh[1024 + j]);
        hp = __half22float2(*(const __half2*)(g_h + (size_t)p * KH + dd));
    }
    float r0 = 1.f / (1.f + expf(-(xr.x + hr.x)));
    float r1 = 1.f / (1.f + expf(-(xr.y + hr.y)));
    float z0 = 1.f / (1.f + expf(-(xz.x + hz.x)));
    float z1 = 1.f / (1.f + expf(-(xz.y + hz.y)));
    float n0 = tanhf(xn.x + r0 * hn.x);
    float n1 = tanhf(xn.y + r1 * hn.y);
    float h0 = (1.f - z0) * n0 + z0 * hp.x;
    float h1 = (1.f - z1) * n1 + z1 * hp.y;
    *(__half2*)(g_h + (size_t)p * KH + dd) = __floats2half2_rn(h0, h1);
    if (g_sln[p] - 1 == t) {
        float* orow = g_out + (size_t)p * KD;
        orow[dd]     = h0;
        orow[dd + 1] = h1;
    }
}

// --------------------------- batchnorm + folded head -----------------------
__global__ void bn_partial() {
    __shared__ float ss[8][33], sq[8][33];
    int col = blockIdx.x * 32 + threadIdx.x;
    int ty = threadIdx.y;
    float s = 0.f, q = 0.f;
    for (int r = blockIdx.y * 8 + ty; r < B_; r += 256) {
        float v = g_out[(size_t)r * KD + col];
        s += v; q += v * v;
    }
    ss[ty][threadIdx.x] = s; sq[ty][threadIdx.x] = q;
    __syncthreads();
    if (ty == 0) {
        float S = 0.f, Q = 0.f;
#pragma unroll
        for (int k = 0; k < 8; k++) { S += ss[k][threadIdx.x]; Q += sq[k][threadIdx.x]; }
        g_psum[blockIdx.y * KD + col] = S;
        g_psq [blockIdx.y * KD + col] = Q;
    }
}

__global__ void weff_kernel(const float* __restrict__ W2, const float* __restrict__ W1) {
    int gw   = blockIdx.x * 8 + (threadIdx.x >> 5);
    int lane = threadIdx.x & 31;
    if (gw >= 2 * D_) return;
    int o = gw / D_, d = gw - o * D_;
    float acc = 0.f;
    for (int j = lane; j < 2 * D_; j += 32)
        acc += W2[o * (2 * D_) + j] * W1[(size_t)j * D_ + d];
#pragma unroll
    for (int off = 16; off; off >>= 1) acc += __shfl_down_sync(0xffffffffu, acc, off);
    if (lane == 0) g_weff[gw] = acc;
}

__global__ void bn_finalize(const float* __restrict__ bn_g, const float* __restrict__ bn_b) {
    int d = blockIdx.x * 256 + threadIdx.x;
    if (d >= D_) return;
    float s = 0.f, q = 0.f;
#pragma unroll
    for (int p = 0; p < 32; p++) { s += g_psum[p * KD + d]; q += g_psq[p * KD + d]; }
    float mu  = s * (1.f / 16384.f);
    float var = fmaxf(q * (1.f / 16384.f) - mu * mu, 0.f);
    float sc  = bn_g[d] * rsqrtf(var + 1e-4f);
    g_shift[d]    = bn_b[d] - mu * sc;
    g_wbn[d]      = g_weff[d]      * sc;
    g_wbn[KD + d] = g_weff[D_ + d] * sc;
}

__global__ void bbn_kernel(const float* __restrict__ W2, const float* __restrict__ b1,
                           const float* __restrict__ b2) {
    int o = blockIdx.x;
    float acc = 0.f;
    for (int j = threadIdx.x; j < 2 * D_; j += 256) acc += W2[o * (2 * D_) + j] * b1[j];
    for (int d = threadIdx.x; d < D_; d += 256)     acc += g_weff[o * D_ + d] * g_shift[d];
    float2 t = block_reduce2(acc, 0.f);
    if (threadIdx.x == 0) g_bbn[o] = t.x + b2[o];
}

__global__ void logits_kernel(float* __restrict__ out) {
    int gw   = (blockIdx.x * 256 + threadIdx.x) >> 5;
    int lane = threadIdx.x & 31;
    if (gw >= B_) return;
    const float* row = g_out + (size_t)gw * KD;
    float a0 = 0.f, a1 = 0.f;
    for (int d = lane; d < D_; d += 32) {
        float v = row[d];
        a0 += v * g_wbn[d];
        a1 += v * g_wbn[KD + d];
    }
#pragma unroll
    for (int o = 16; o; o >>= 1) {
        a0 += __shfl_down_sync(0xffffffffu, a0, o);
        a1 += __shfl_down_sync(0xffffffffu, a1, o);
    }
    if (lane == 0) {
        int b = g_idx[gw];
        out[2 * b]     = a0 + g_bbn[0];
        out[2 * b + 1] = a1 + g_bbn[1];
    }
}

// --------------------------- launch -----------------------------------------
extern "C" void kernel_launch(void* const* d_in, const int* in_sizes, int n_in,
                              void* d_out, int out_size) {
    const int*   node_seq   = (const int*)d_in[0];
    const int*   fin_seq    = (const int*)d_in[1];
    const int*   nfin_seq   = (const int*)d_in[2];
    const int*   mda_seq    = (const int*)d_in[3];
    const int*   seq_len    = (const int*)d_in[4];
    const float* node_table = (const float*)d_in[5];
    const float* fin_table  = (const float*)d_in[6];
    const float* nfin_table = (const float*)d_in[7];
    const float* bert_table = (const float*)d_in[8];
    const float* ln_g = (const float*)d_in[9];
    const float* ln_b = (const float*)d_in[10];
    const float* W_ih = (const float*)d_in[11];
    const float* W_hh = (const float*)d_in[12];
    const float* b_ih = (const float*)d_in[13];
    const float* b_hh = (const float*)d_in[14];
    const float* bn_g = (const float*)d_in[15];
    const float* bn_b = (const float*)d_in[16];
    const float* W1   = (const float*)d_in[17];
    const float* b1   = (const float*)d_in[18];
    const float* W2   = (const float*)d_in[19];
    const float* b2   = (const float*)d_in[20];

    __half *px, *pxg, *pgh, *ph, *pWih, *pWhh;
    float *pbih, *pbhh;
    cudaGetSymbolAddress((void**)&px,   g_x);
    cudaGetSymbolAddress((void**)&pxg,  g_xg);
    cudaGetSymbolAddress((void**)&pgh,  g_gh);
    cudaGetSymbolAddress((void**)&ph,   g_h);
    cudaGetSymbolAddress((void**)&pWih, g_Wih);
    cudaGetSymbolAddress((void**)&pWhh, g_Whh);
    cudaGetSymbolAddress((void**)&pbih, g_bih);
    cudaGetSymbolAddress((void**)&pbhh, g_bhh);

    cudaFuncSetAttribute(gemm_h, cudaFuncAttributeMaxDynamicSharedMemorySize, SMEMB);

    sort_kernel<<<1, 1024>>>(seq_len);
    pad_weights<<<(NP * KH + 255) / 256, 256>>>(W_ih, W_hh, b_ih, b_hh);
    embed_ln<<<B_ * S_, 256>>>(node_seq, fin_seq, nfin_seq, mda_seq,
                               node_table, fin_table, nfin_table, bert_table,
                               ln_g, ln_b);

    // GEMM1: xg = x @ W_ih^T + b_ih  (ragged: per-s active prefix)
    gemm_h<<<(B_ * S_ / TM) * NT_, 256, SMEMB>>>(px, pWih, pxg, pbih, -1);

    // GRU: t=0 uses h0=0 => gh = b_hh, no GEMM needed
    gru_cell<<<(B_ * 496 + 1023) / 1024, 1024>>>(0, 1);
    for (int t = 1; t < S_; ++t) {
        gemm_h<<<(B_ / TM) * NT_, 256, SMEMB>>>(ph, pWhh, pgh, pbhh, t);
        gru_cell<<<(B_ * 496 + 1023) / 1024, 1024>>>(t, 0);
    }

    // head constant-folding (independent; late so ncu slot catches gemm_h)
    weff_kernel<<<(2 * D_ + 7) / 8, 256>>>(W2, W1);

    // batchnorm stats + folded head
    bn_partial<<<dim3(31, 32), dim3(32, 8)>>>();
    bn_finalize<<<(D_ + 255) / 256, 256>>>(bn_g, bn_b);
    bbn_kernel<<<2, 256>>>(W2, b1, b2);
    logits_kernel<<<(B_ * 32 + 255) / 256, 256>>>((float*)d_out);
}